// round 14
// baseline (speedup 1.0000x reference)
#include <cuda_runtime.h>
#include <cuda_bf16.h>
#include <cuda_fp16.h>
#include <cstdint>

#define BATCH 16
#define SEQ   512
#define DIM   64
#define L2E 1.4426950408889634f

// ------------------------- global scratch (static) -------------------------
__device__ float g_s[BATCH * SEQ * SEQ];      // 16 MB logits
__device__ float g_xout[BATCH * SEQ * DIM];   // pre-BN output
__device__ float g_part[128 * 64];            // BN partial sums
__device__ float g_partsq[128 * 64];          // BN partial sumsq
__device__ float g_bnscale[DIM];
__device__ float g_bnbias[DIM];

// ------------------------------ helpers ------------------------------------
__device__ __forceinline__ uint32_t smem_u32(const void* p) {
    uint32_t a;
    asm("{ .reg .u64 t; cvta.to.shared.u64 t, %1; cvt.u32.u64 %0, t; }" : "=r"(a) : "l"(p));
    return a;
}
__device__ __forceinline__ float ex2f(float x) { float r; asm("ex2.approx.f32 %0, %1;" : "=f"(r) : "f"(x)); return r; }
__device__ __forceinline__ float tanhf_a(float x) { float r; asm("tanh.approx.f32 %0, %1;" : "=f"(r) : "f"(x)); return r; }
__device__ __forceinline__ uint32_t pack_h2(float a, float b) {
    __half2 h = __floats2half2_rn(a, b);
    return *reinterpret_cast<uint32_t*>(&h);
}
__device__ __forceinline__ uint32_t hmul2u(uint32_t a, uint32_t b) {
    __half2 r = __hmul2(*reinterpret_cast<__half2*>(&a), *reinterpret_cast<__half2*>(&b));
    return *reinterpret_cast<uint32_t*>(&r);
}
__device__ __forceinline__ void ldsm4(uint32_t* r, uint32_t addr) {
    asm volatile("ldmatrix.sync.aligned.m8n8.x4.shared.b16 {%0,%1,%2,%3}, [%4];"
        : "=r"(r[0]), "=r"(r[1]), "=r"(r[2]), "=r"(r[3]) : "r"(addr));
}
__device__ __forceinline__ void ldsm4t(uint32_t* r, uint32_t addr) {
    asm volatile("ldmatrix.sync.aligned.m8n8.x4.trans.shared.b16 {%0,%1,%2,%3}, [%4];"
        : "=r"(r[0]), "=r"(r[1]), "=r"(r[2]), "=r"(r[3]) : "r"(addr));
}
__device__ __forceinline__ void mma16816h(float* d, const uint32_t* a, uint32_t b0, uint32_t b1) {
    asm volatile("mma.sync.aligned.m16n8k16.row.col.f32.f16.f16.f32 "
        "{%0,%1,%2,%3}, {%4,%5,%6,%7}, {%8,%9}, {%0,%1,%2,%3};"
        : "+f"(d[0]), "+f"(d[1]), "+f"(d[2]), "+f"(d[3])
        : "r"(a[0]), "r"(a[1]), "r"(a[2]), "r"(a[3]), "r"(b0), "r"(b1));
}

// ---------------------------------------------------------------------------
// Kernel 1: symmetric score tiles — 8 warps/block, o-split, split-kt chains.
//   Z[j,o] = sum_d P[j,d] W[o,d],  P[j,d] = fp16(x_j[d]) * fp16(x_i[d])
// grid = 16 b x 36 tile pairs (ti<=tj), block 256.
// Warp (jw, oh): j-rows [16jw,16jw+16), o-cols [32oh,32oh+32).
// Two independent accumulator sets D (kt 0,2) / E (kt 1,3) halve the serial
// HMMA dependency depth; z = D + E at the epilogue.
// ---------------------------------------------------------------------------
#define SXI 0
#define SW  8192
#define ST0 17408
#define ST1 34048
#define SBC 50688
#define SVS 50944
#define SC_SMEM 51200

__global__ void __launch_bounds__(256, 2)
score_kernel(const float* __restrict__ x, const float* __restrict__ W,
             const float* __restrict__ bias, const float* __restrict__ v)
{
    extern __shared__ __align__(16) char sm[];
    const uint32_t sb = smem_u32(sm);
    uint32_t* XiU = (uint32_t*)(sm + SXI);   // half2 view, 64 rows x 32 words
    uint32_t* XjU = (uint32_t*)(sm + ST0);   // staged in St0 region
    uint32_t* WU  = (uint32_t*)(sm + SW);    // half2 view, pitch 36 u32/row
    float*    St0 = (float*)(sm + ST0);      // o 0..31 partial
    float*    St1 = (float*)(sm + ST1);      // o 32..63 partial
    float*    bcs = (float*)(sm + SBC);
    float*    vss = (float*)(sm + SVS);

    const int tid = threadIdx.x;
    const int wid = tid >> 5, l = tid & 31;
    const int jw = wid >> 1, oh = wid & 1;

    const int b = blockIdx.x / 36;
    int p = blockIdx.x % 36;
    int ti = 0;
    while (p >= 8 - ti) { p -= 8 - ti; ti++; }
    const int tj = ti + p;
    const int i0 = ti * 64, j0 = tj * 64;
    const float* xb = x + b * SEQ * DIM;

    // ---- stage Xi, Xj (half2), W (half, 144B pitch), consts ----
    for (int e = tid; e < 2048; e += 256) {
        const int r = e >> 5, c2 = e & 31;
        float2 fi = *(const float2*)(xb + (i0 + r) * DIM + c2 * 2);
        float2 fj = *(const float2*)(xb + (j0 + r) * DIM + c2 * 2);
        float2 fw = *(const float2*)(W + r * 64 + c2 * 2);
        XiU[e] = pack_h2(fi.x, fi.y);
        XjU[e] = pack_h2(fj.x, fj.y);
        WU[r * 36 + c2] = pack_h2(fw.x, fw.y);
    }
    if (tid < 64) { bcs[tid] = bias[tid]; vss[tid] = v[tid]; }
    __syncthreads();

    const int c0 = (l & 3) * 2;
    const int rr = l >> 2;
    const int r0 = jw * 16 + rr;

    // ---- B-frags: this warp's 32 o-rows of W via ldmatrix, once ----
    const uint32_t boff_lane = (uint32_t)((l & 7) + ((l & 16) ? 8 : 0)) * 144
                             + ((l & 8) ? 16u : 0u);
    uint32_t wb0[4][4], wb1[4][4];
    #pragma unroll
    for (int kt = 0; kt < 4; kt++) {
        #pragma unroll
        for (int npl = 0; npl < 2; npl++) {
            uint32_t t[4];
            ldsm4(t, sb + SW + (uint32_t)(oh * 32 + npl * 16) * 144
                     + boff_lane + kt * 32);
            wb0[2*npl][kt]   = t[0]; wb1[2*npl][kt]   = t[1];
            wb0[2*npl+1][kt] = t[2]; wb1[2*npl+1][kt] = t[3];
        }
    }

    // ---- epilogue constants: v in f32 regs, bias packed half2 ----
    float vvr[4][2];
    __half2 bcp[4];
    #pragma unroll
    for (int nt = 0; nt < 4; nt++) {
        const int ob = oh * 32 + nt * 8 + c0;
        vvr[nt][0] = vss[ob];
        vvr[nt][1] = vss[ob + 1];
        bcp[nt] = __floats2half2_rn(bcs[ob], bcs[ob + 1]);
    }

    // ---- x_j half2 regs ----
    uint32_t xjA[4], xjB[4], xjC[4], xjD[4];
    #pragma unroll
    for (int kt = 0; kt < 4; kt++) {
        xjA[kt] = XjU[r0 * 32 + kt * 8 + (l & 3)];
        xjB[kt] = XjU[r0 * 32 + kt * 8 + (l & 3) + 4];
        xjC[kt] = XjU[(r0 + 8) * 32 + kt * 8 + (l & 3)];
        xjD[kt] = XjU[(r0 + 8) * 32 + kt * 8 + (l & 3) + 4];
    }
    __syncthreads();   // St0 region (Xj staging) now reusable

    float* StW = oh ? St1 : St0;

    // ---- main loop over i (no block barriers) ----
    for (int ii = 0; ii < 64; ii++) {
        uint32_t xiA[4], xiB[4];
        #pragma unroll
        for (int kt = 0; kt < 4; kt++) {
            xiA[kt] = XiU[ii * 32 + kt * 8 + (l & 3)];
            xiB[kt] = XiU[ii * 32 + kt * 8 + (l & 3) + 4];
        }

        // Two accumulator sets: D (bias-init, kt 0,2), E (zero-init, kt 1,3)
        float D[4][4], E[4][4];
        #pragma unroll
        for (int nt = 0; nt < 4; nt++) {
            float2 bc2 = __half22float2(bcp[nt]);
            D[nt][0] = bc2.x; D[nt][1] = bc2.y;
            D[nt][2] = bc2.x; D[nt][3] = bc2.y;
            E[nt][0] = 0.f; E[nt][1] = 0.f; E[nt][2] = 0.f; E[nt][3] = 0.f;
        }

        #pragma unroll
        for (int kt = 0; kt < 4; kt++) {
            uint32_t ah[4];
            ah[0] = hmul2u(xjA[kt], xiA[kt]);
            ah[1] = hmul2u(xjC[kt], xiA[kt]);
            ah[2] = hmul2u(xjB[kt], xiB[kt]);
            ah[3] = hmul2u(xjD[kt], xiB[kt]);
            float (*acc)[4] = (kt & 1) ? E : D;
            #pragma unroll
            for (int nt = 0; nt < 4; nt++)
                mma16816h(acc[nt], ah, wb0[nt][kt], wb1[nt][kt]);
        }

        // ---- epilogue: partial s over this warp's 32 o's (z = D + E) ----
        float s0 = 0.f, s1 = 0.f;
        #pragma unroll
        for (int nt = 0; nt < 4; nt++) {
            #pragma unroll
            for (int e = 0; e < 2; e++) {
                s0 = fmaf(vvr[nt][e], tanhf_a(D[nt][e]     + E[nt][e]),     s0);
                s1 = fmaf(vvr[nt][e], tanhf_a(D[nt][2 + e] + E[nt][2 + e]), s1);
            }
        }
        s0 += __shfl_xor_sync(~0u, s0, 1);
        s0 += __shfl_xor_sync(~0u, s0, 2);
        s1 += __shfl_xor_sync(~0u, s1, 1);
        s1 += __shfl_xor_sync(~0u, s1, 2);
        if ((l & 3) == 0) {
            StW[ii * 65 + r0]     = s0;
            StW[ii * 65 + r0 + 8] = s1;
        }
    }

    __syncthreads();

    // ---- write out S tile = St0 + St1 (+ transpose for off-diagonal) ----
    for (int e = tid; e < 4096; e += 256) {
        const int i = e >> 6, j = e & 63;
        const float sv = St0[i * 65 + j] + St1[i * 65 + j];
        g_s[((size_t)(b * SEQ + i0 + i)) * SEQ + (j0 + j)] = sv;
        if (ti != tj)
            g_s[((size_t)(b * SEQ + j0 + j)) * SEQ + (i0 + i)] = sv;
    }
}

// ---------------------------------------------------------------------------
// Kernel 2: softmax + tensor-core aggregate + projections + BN partials.
// (unchanged from R12 — ncu 33.9us)
// ---------------------------------------------------------------------------
#define PH  0
#define XH  68608
#define AGP 142336
#define W1T 158720
#define W2T 176128
#define ABB 193536
#define APT 193792
#define AG_SMEM 197888

__global__ void __launch_bounds__(512, 1)
agg_kernel(const float* __restrict__ x,
           const float* __restrict__ Wwith, const float* __restrict__ bwith,
           const float* __restrict__ Wwo,   const float* __restrict__ bwo)
{
    extern __shared__ __align__(16) char sm[];
    const uint32_t sb = smem_u32(sm);
    __half*   ph  = (__half*)(sm + PH);
    uint32_t* xhw = (uint32_t*)(sm + XH);    // word view, pitch 36 words/row
    float*    agg = (float*)(sm + AGP);
    float*    w1t = (float*)(sm + W1T);
    float*    w2t = (float*)(sm + W2T);
    float*    bb  = (float*)(sm + ABB);
    float*    pt  = (float*)(sm + APT);

    const int tid = threadIdx.x;
    const int b  = blockIdx.x >> 3;
    const int i0 = (blockIdx.x & 7) * 64;
    const float* xb = x + b * SEQ * DIM;

    // ---- stage weights (o-major, pitch 68) + combined bias ----
    for (int t = tid; t < 1024; t += 512) {
        const int o = t >> 4, dq = t & 15;
        *(float4*)(w1t + o * 68 + dq * 4) = *(const float4*)(Wwith + o * 64 + dq * 4);
        *(float4*)(w2t + o * 68 + dq * 4) = *(const float4*)(Wwo   + o * 64 + dq * 4);
    }
    if (tid < 64) bb[tid] = bwith[tid] + bwo[tid];

    // ---- stage x row-major fp16 (coalesced reads, conflict-free writes) ----
    for (int t = tid; t < 16384; t += 512) {
        const int j = t >> 5, c2 = t & 31;
        float2 f = *(const float2*)(xb + j * 64 + c2 * 2);
        xhw[j * 36 + c2] = pack_h2(f.x, f.y);
    }

    // ---- softmax: 64 rows in 2 passes of 32 (16 threads/row) ----
    #pragma unroll
    for (int pass = 0; pass < 2; pass++) {
        const int il = (tid >> 4) + pass * 32;
        const int sub = tid & 15;
        const float* sr = g_s + ((size_t)(b * SEQ + i0 + il)) * SEQ;
        float vals[32];
        float m = -1e30f;
        #pragma unroll
        for (int k = 0; k < 32; k++) {
            vals[k] = sr[k * 16 + sub];
            m = fmaxf(m, vals[k]);
        }
        #pragma unroll
        for (int off = 8; off; off >>= 1) m = fmaxf(m, __shfl_xor_sync(~0u, m, off));
        float ssum = 0.f;
        #pragma unroll
        for (int k = 0; k < 32; k++) {
            vals[k] = ex2f((vals[k] - m) * L2E);
            ssum += vals[k];
        }
        #pragma unroll
        for (int off = 8; off; off >>= 1) ssum += __shfl_xor_sync(~0u, ssum, off);
        const float rs = 1.0f / ssum;
        #pragma unroll
        for (int k = 0; k < 32; k++)
            ph[il * 536 + k * 16 + sub] = __float2half(vals[k] * rs);
    }
    __syncthreads();

    // ---- tensor-core aggregate ----
    {
        const int wid = tid >> 5, l = tid & 31;
        const int mt = wid >> 2, nt4 = wid & 3;
        const uint32_t pha = sb + PH
            + ((uint32_t)(mt * 16 + (l & 7) + ((l >> 3) & 1) * 8) * 536
               + ((l >> 4) & 1) * 8) * 2;
        const uint32_t xba = sb + XH
            + (uint32_t)(l & 15) * 144 + (uint32_t)(l >> 4) * 16
            + (uint32_t)nt4 * 32;

        float DA[2][4] = {{0.f,0.f,0.f,0.f},{0.f,0.f,0.f,0.f}};
        #pragma unroll 4
        for (int k16 = 0; k16 < 32; k16++) {
            uint32_t a[4];
            ldsm4(a, pha + k16 * 32);
            uint32_t bfr[4];
            ldsm4t(bfr, xba + k16 * 2304);   // 16 rows * 144B
            mma16816h(DA[0], a, bfr[0], bfr[1]);
            mma16816h(DA[1], a, bfr[2], bfr[3]);
        }
        const int row = mt * 16 + (l >> 2);
        #pragma unroll
        for (int nt8 = 0; nt8 < 2; nt8++) {
            const int col = nt4 * 16 + nt8 * 8 + (l & 3) * 2;
            *(float2*)(agg + row * 64 + col)       = make_float2(DA[nt8][0], DA[nt8][1]);
            *(float2*)(agg + (row + 8) * 64 + col) = make_float2(DA[nt8][2], DA[nt8][3]);
        }
    }
    __syncthreads();

    // ---- projections + BN partials ----
    {
        const int o = tid & 63, iq = tid >> 6;
        const float* wo1 = w1t + o * 68;
        const float* wo2 = w2t + o * 68;
        const float bo = bb[o];
        float psum = 0.f, psq = 0.f;
        #pragma unroll
        for (int m2 = 0; m2 < 8; m2++) {
            const int i = iq + 8 * m2;
            const float* ag = agg + i * 64;
            const float* xr = xb + (i0 + i) * DIM;
            float r0 = bo, r1 = 0.f;
            #pragma unroll
            for (int dd = 0; dd < 64; dd += 4) {
                float4 av = *(const float4*)(ag + dd);
                float4 w1 = *(const float4*)(wo1 + dd);
                float4 xv = *(const float4*)(xr + dd);
                float4 w2 = *(const float4*)(wo2 + dd);
                r0 = fmaf(av.x, w1.x, r0); r1 = fmaf(av.y, w1.y, r1);
                r0 = fmaf(av.z, w1.z, r0); r1 = fmaf(av.w, w1.w, r1);
                r0 = fmaf(xv.x, w2.x, r0); r1 = fmaf(xv.y, w2.y, r1);
                r0 = fmaf(xv.z, w2.z, r0); r1 = fmaf(xv.w, w2.w, r1);
            }
            const float r = r0 + r1;
            g_xout[((size_t)(b * SEQ + i0 + i)) * DIM + o] = r;
            psum += r;
            psq = fmaf(r, r, psq);
        }
        pt[iq * 64 + o]       = psum;
        pt[512 + iq * 64 + o] = psq;
    }
    __syncthreads();
    if (tid < 64) {
        float s = 0.f, sq = 0.f;
        #pragma unroll
        for (int q = 0; q < 8; q++) {
            s  += pt[q * 64 + tid];
            sq += pt[512 + q * 64 + tid];
        }
        g_part[blockIdx.x * 64 + tid]   = s;
        g_partsq[blockIdx.x * 64 + tid] = sq;
    }
}

// ---------------------------------------------------------------------------
// Kernel 3: BN finalize
// ---------------------------------------------------------------------------
__global__ void __launch_bounds__(128)
bnfin_kernel(const float* __restrict__ gamma, const float* __restrict__ beta)
{
    __shared__ float rs[4], rq[4];
    const int o = blockIdx.x, tid = threadIdx.x;
    float s = 0.f, sq = 0.f;
    for (int k = tid; k < 128; k += 128) {
        s  += g_part[k * 64 + o];
        sq += g_partsq[k * 64 + o];
    }
    #pragma unroll
    for (int off = 16; off; off >>= 1) {
        s  += __shfl_xor_sync(~0u, s, off);
        sq += __shfl_xor_sync(~0u, sq, off);
    }
    if ((tid & 31) == 0) { rs[tid >> 5] = s; rq[tid >> 5] = sq; }
    __syncthreads();
    if (tid == 0) {
        float ts = rs[0] + rs[1] + rs[2] + rs[3];
        float tq = rq[0] + rq[1] + rq[2] + rq[3];
        const float inv = 1.0f / (BATCH * SEQ);
        float mean = ts * inv;
        float var  = tq * inv - mean * mean;
        float sc = gamma[o] * rsqrtf(var + 1e-5f);
        g_bnscale[o] = sc;
        g_bnbias[o]  = beta[o] - mean * sc;
    }
}

// ---------------------------------------------------------------------------
// Kernel 4: normalize + SELU -> d_out
// ---------------------------------------------------------------------------
__global__ void __launch_bounds__(256)
apply_kernel(float* __restrict__ out)
{
    const int idx = blockIdx.x * 256 + threadIdx.x;
    const int o = idx & 63;
    float v = fmaf(g_xout[idx], g_bnscale[o], g_bnbias[o]);
    const float SC = 1.0507009873554805f, AL = 1.6732632423543772f;
    float neg = SC * AL * (ex2f(v * L2E) - 1.0f);
    out[idx] = v > 0.f ? SC * v : neg;
}

// ---------------------------------------------------------------------------
extern "C" void kernel_launch(void* const* d_in, const int* in_sizes, int n_in,
                              void* d_out, int out_size)
{
    const float* x      = (const float*)d_in[0];
    const float* Wattp  = (const float*)d_in[1];
    const float* battp  = (const float*)d_in[2];
    const float* attw   = (const float*)d_in[3];
    const float* Wwith  = (const float*)d_in[4];
    const float* bwith  = (const float*)d_in[5];
    const float* Wwo    = (const float*)d_in[6];
    const float* bwo    = (const float*)d_in[7];
    const float* gamma  = (const float*)d_in[8];
    const float* beta   = (const float*)d_in[9];
    float* out = (float*)d_out;

    cudaFuncSetAttribute(score_kernel, cudaFuncAttributeMaxDynamicSharedMemorySize, SC_SMEM);
    cudaFuncSetAttribute(agg_kernel,   cudaFuncAttributeMaxDynamicSharedMemorySize, AG_SMEM);

    score_kernel<<<BATCH * 36, 256, SC_SMEM>>>(x, Wattp, battp, attw);
    agg_kernel<<<128, 512, AG_SMEM>>>(x, Wwith, bwith, Wwo, bwo);
    bnfin_kernel<<<64, 128>>>(gamma, beta);
    apply_kernel<<<BATCH * SEQ * DIM / 256, 256>>>(out);
}

// round 15
// speedup vs baseline: 1.1687x; 1.1687x over previous
#include <cuda_runtime.h>
#include <cuda_bf16.h>
#include <cuda_fp16.h>
#include <cstdint>

#define BATCH 16
#define SEQ   512
#define DIM   64
#define L2E 1.4426950408889634f

// ------------------------- global scratch (static) -------------------------
__device__ float g_s[BATCH * SEQ * SEQ];      // 16 MB logits
__device__ float g_xout[BATCH * SEQ * DIM];   // pre-BN output
__device__ float g_part[128 * 64];            // BN partial sums
__device__ float g_partsq[128 * 64];          // BN partial sumsq
__device__ float g_bnscale[DIM];
__device__ float g_bnbias[DIM];

// ------------------------------ helpers ------------------------------------
__device__ __forceinline__ uint32_t smem_u32(const void* p) {
    uint32_t a;
    asm("{ .reg .u64 t; cvta.to.shared.u64 t, %1; cvt.u32.u64 %0, t; }" : "=r"(a) : "l"(p));
    return a;
}
__device__ __forceinline__ float ex2f(float x) { float r; asm("ex2.approx.f32 %0, %1;" : "=f"(r) : "f"(x)); return r; }
__device__ __forceinline__ float tanhf_a(float x) { float r; asm("tanh.approx.f32 %0, %1;" : "=f"(r) : "f"(x)); return r; }
__device__ __forceinline__ uint32_t pack_h2(float a, float b) {
    __half2 h = __floats2half2_rn(a, b);
    return *reinterpret_cast<uint32_t*>(&h);
}
__device__ __forceinline__ uint32_t hmul2u(uint32_t a, uint32_t b) {
    __half2 r = __hmul2(*reinterpret_cast<__half2*>(&a), *reinterpret_cast<__half2*>(&b));
    return *reinterpret_cast<uint32_t*>(&r);
}
__device__ __forceinline__ void ldsm4(uint32_t* r, uint32_t addr) {
    asm volatile("ldmatrix.sync.aligned.m8n8.x4.shared.b16 {%0,%1,%2,%3}, [%4];"
        : "=r"(r[0]), "=r"(r[1]), "=r"(r[2]), "=r"(r[3]) : "r"(addr));
}
__device__ __forceinline__ void ldsm4t(uint32_t* r, uint32_t addr) {
    asm volatile("ldmatrix.sync.aligned.m8n8.x4.trans.shared.b16 {%0,%1,%2,%3}, [%4];"
        : "=r"(r[0]), "=r"(r[1]), "=r"(r[2]), "=r"(r[3]) : "r"(addr));
}
__device__ __forceinline__ void mma16816h(float* d, const uint32_t* a, uint32_t b0, uint32_t b1) {
    asm volatile("mma.sync.aligned.m16n8k16.row.col.f32.f16.f16.f32 "
        "{%0,%1,%2,%3}, {%4,%5,%6,%7}, {%8,%9}, {%0,%1,%2,%3};"
        : "+f"(d[0]), "+f"(d[1]), "+f"(d[2]), "+f"(d[3])
        : "r"(a[0]), "r"(a[1]), "r"(a[2]), "r"(a[3]), "r"(b0), "r"(b1));
}

// ---------------------------------------------------------------------------
// Kernel 1: symmetric score tiles — R13 form (measured 70.8us, regs 110).
//   Z[j,o] = sum_d P[j,d] W[o,d],  P[j,d] = fp16(x_j[d]) * fp16(x_i[d])
// grid = 16 b x 36 tile pairs (ti<=tj), block 256 (8 warps).
// Warp (jw, oh): j-rows [16jw,16jw+16), o-cols [32oh,32oh+32).
// ---------------------------------------------------------------------------
#define SXI 0
#define SW  8192
#define ST0 17408
#define ST1 34048
#define SBC 50688
#define SVS 50944
#define SC_SMEM 51200

__global__ void __launch_bounds__(256, 2)
score_kernel(const float* __restrict__ x, const float* __restrict__ W,
             const float* __restrict__ bias, const float* __restrict__ v)
{
    extern __shared__ __align__(16) char sm[];
    const uint32_t sb = smem_u32(sm);
    uint32_t* XiU = (uint32_t*)(sm + SXI);   // half2 view, 64 rows x 32 words
    uint32_t* XjU = (uint32_t*)(sm + ST0);   // staged in St0 region
    uint32_t* WU  = (uint32_t*)(sm + SW);    // half2 view, pitch 36 u32/row
    float*    St0 = (float*)(sm + ST0);      // o 0..31 partial
    float*    St1 = (float*)(sm + ST1);      // o 32..63 partial
    float*    bcs = (float*)(sm + SBC);
    float*    vss = (float*)(sm + SVS);

    const int tid = threadIdx.x;
    const int wid = tid >> 5, l = tid & 31;
    const int jw = wid >> 1, oh = wid & 1;

    const int b = blockIdx.x / 36;
    int p = blockIdx.x % 36;
    int ti = 0;
    while (p >= 8 - ti) { p -= 8 - ti; ti++; }
    const int tj = ti + p;
    const int i0 = ti * 64, j0 = tj * 64;
    const float* xb = x + b * SEQ * DIM;

    // ---- stage Xi, Xj (half2), W (half, 144B pitch), consts ----
    for (int e = tid; e < 2048; e += 256) {
        const int r = e >> 5, c2 = e & 31;
        float2 fi = *(const float2*)(xb + (i0 + r) * DIM + c2 * 2);
        float2 fj = *(const float2*)(xb + (j0 + r) * DIM + c2 * 2);
        float2 fw = *(const float2*)(W + r * 64 + c2 * 2);
        XiU[e] = pack_h2(fi.x, fi.y);
        XjU[e] = pack_h2(fj.x, fj.y);
        WU[r * 36 + c2] = pack_h2(fw.x, fw.y);
    }
    if (tid < 64) { bcs[tid] = bias[tid]; vss[tid] = v[tid]; }
    __syncthreads();

    const int c0 = (l & 3) * 2;
    const int rr = l >> 2;
    const int r0 = jw * 16 + rr;

    // ---- B-frags: this warp's 32 o-rows of W via ldmatrix, once ----
    const uint32_t boff_lane = (uint32_t)((l & 7) + ((l & 16) ? 8 : 0)) * 144
                             + ((l & 8) ? 16u : 0u);
    uint32_t wb0[4][4], wb1[4][4];
    #pragma unroll
    for (int kt = 0; kt < 4; kt++) {
        #pragma unroll
        for (int npl = 0; npl < 2; npl++) {
            uint32_t t[4];
            ldsm4(t, sb + SW + (uint32_t)(oh * 32 + npl * 16) * 144
                     + boff_lane + kt * 32);
            wb0[2*npl][kt]   = t[0]; wb1[2*npl][kt]   = t[1];
            wb0[2*npl+1][kt] = t[2]; wb1[2*npl+1][kt] = t[3];
        }
    }

    // ---- epilogue constants: v in f32 regs, bias packed half2 ----
    float vvr[4][2];
    __half2 bcp[4];
    #pragma unroll
    for (int nt = 0; nt < 4; nt++) {
        const int ob = oh * 32 + nt * 8 + c0;
        vvr[nt][0] = vss[ob];
        vvr[nt][1] = vss[ob + 1];
        bcp[nt] = __floats2half2_rn(bcs[ob], bcs[ob + 1]);
    }

    // ---- x_j half2 regs ----
    uint32_t xjA[4], xjB[4], xjC[4], xjD[4];
    #pragma unroll
    for (int kt = 0; kt < 4; kt++) {
        xjA[kt] = XjU[r0 * 32 + kt * 8 + (l & 3)];
        xjB[kt] = XjU[r0 * 32 + kt * 8 + (l & 3) + 4];
        xjC[kt] = XjU[(r0 + 8) * 32 + kt * 8 + (l & 3)];
        xjD[kt] = XjU[(r0 + 8) * 32 + kt * 8 + (l & 3) + 4];
    }
    __syncthreads();   // St0 region (Xj staging) now reusable

    float* StW = oh ? St1 : St0;

    // ---- main loop over i (no block barriers) ----
    for (int ii = 0; ii < 64; ii++) {
        uint32_t xiA[4], xiB[4];
        #pragma unroll
        for (int kt = 0; kt < 4; kt++) {
            xiA[kt] = XiU[ii * 32 + kt * 8 + (l & 3)];
            xiB[kt] = XiU[ii * 32 + kt * 8 + (l & 3) + 4];
        }

        // D init = bias (accumulate z + b directly)
        float D[4][4];
        #pragma unroll
        for (int nt = 0; nt < 4; nt++) {
            float2 bc2 = __half22float2(bcp[nt]);
            D[nt][0] = bc2.x; D[nt][1] = bc2.y;
            D[nt][2] = bc2.x; D[nt][3] = bc2.y;
        }

        #pragma unroll
        for (int kt = 0; kt < 4; kt++) {
            uint32_t ah[4];
            ah[0] = hmul2u(xjA[kt], xiA[kt]);
            ah[1] = hmul2u(xjC[kt], xiA[kt]);
            ah[2] = hmul2u(xjB[kt], xiB[kt]);
            ah[3] = hmul2u(xjD[kt], xiB[kt]);
            #pragma unroll
            for (int nt = 0; nt < 4; nt++)
                mma16816h(D[nt], ah, wb0[nt][kt], wb1[nt][kt]);
        }

        // ---- epilogue: partial s over this warp's 32 o's ----
        float s0 = 0.f, s1 = 0.f;
        #pragma unroll
        for (int nt = 0; nt < 4; nt++) {
            #pragma unroll
            for (int e = 0; e < 2; e++) {
                s0 = fmaf(vvr[nt][e], tanhf_a(D[nt][e]),     s0);
                s1 = fmaf(vvr[nt][e], tanhf_a(D[nt][2 + e]), s1);
            }
        }
        s0 += __shfl_xor_sync(~0u, s0, 1);
        s0 += __shfl_xor_sync(~0u, s0, 2);
        s1 += __shfl_xor_sync(~0u, s1, 1);
        s1 += __shfl_xor_sync(~0u, s1, 2);
        if ((l & 3) == 0) {
            StW[ii * 65 + r0]     = s0;
            StW[ii * 65 + r0 + 8] = s1;
        }
    }

    __syncthreads();

    // ---- write out S tile = St0 + St1 (+ transpose for off-diagonal) ----
    for (int e = tid; e < 4096; e += 256) {
        const int i = e >> 6, j = e & 63;
        const float sv = St0[i * 65 + j] + St1[i * 65 + j];
        g_s[((size_t)(b * SEQ + i0 + i)) * SEQ + (j0 + j)] = sv;
        if (ti != tj)
            g_s[((size_t)(b * SEQ + j0 + j)) * SEQ + (i0 + i)] = sv;
    }
}

// ---------------------------------------------------------------------------
// Kernel 2: softmax + tensor-core aggregate + projections + BN partials.
// (unchanged from R12 — ncu 33.9us)
// ---------------------------------------------------------------------------
#define PH  0
#define XH  68608
#define AGP 142336
#define W1T 158720
#define W2T 176128
#define ABB 193536
#define APT 193792
#define AG_SMEM 197888

__global__ void __launch_bounds__(512, 1)
agg_kernel(const float* __restrict__ x,
           const float* __restrict__ Wwith, const float* __restrict__ bwith,
           const float* __restrict__ Wwo,   const float* __restrict__ bwo)
{
    extern __shared__ __align__(16) char sm[];
    const uint32_t sb = smem_u32(sm);
    __half*   ph  = (__half*)(sm + PH);
    uint32_t* xhw = (uint32_t*)(sm + XH);    // word view, pitch 36 words/row
    float*    agg = (float*)(sm + AGP);
    float*    w1t = (float*)(sm + W1T);
    float*    w2t = (float*)(sm + W2T);
    float*    bb  = (float*)(sm + ABB);
    float*    pt  = (float*)(sm + APT);

    const int tid = threadIdx.x;
    const int b  = blockIdx.x >> 3;
    const int i0 = (blockIdx.x & 7) * 64;
    const float* xb = x + b * SEQ * DIM;

    // ---- stage weights (o-major, pitch 68) + combined bias ----
    for (int t = tid; t < 1024; t += 512) {
        const int o = t >> 4, dq = t & 15;
        *(float4*)(w1t + o * 68 + dq * 4) = *(const float4*)(Wwith + o * 64 + dq * 4);
        *(float4*)(w2t + o * 68 + dq * 4) = *(const float4*)(Wwo   + o * 64 + dq * 4);
    }
    if (tid < 64) bb[tid] = bwith[tid] + bwo[tid];

    // ---- stage x row-major fp16 (coalesced reads, conflict-free writes) ----
    for (int t = tid; t < 16384; t += 512) {
        const int j = t >> 5, c2 = t & 31;
        float2 f = *(const float2*)(xb + j * 64 + c2 * 2);
        xhw[j * 36 + c2] = pack_h2(f.x, f.y);
    }

    // ---- softmax: 64 rows in 2 passes of 32 (16 threads/row) ----
    #pragma unroll
    for (int pass = 0; pass < 2; pass++) {
        const int il = (tid >> 4) + pass * 32;
        const int sub = tid & 15;
        const float* sr = g_s + ((size_t)(b * SEQ + i0 + il)) * SEQ;
        float vals[32];
        float m = -1e30f;
        #pragma unroll
        for (int k = 0; k < 32; k++) {
            vals[k] = sr[k * 16 + sub];
            m = fmaxf(m, vals[k]);
        }
        #pragma unroll
        for (int off = 8; off; off >>= 1) m = fmaxf(m, __shfl_xor_sync(~0u, m, off));
        float ssum = 0.f;
        #pragma unroll
        for (int k = 0; k < 32; k++) {
            vals[k] = ex2f((vals[k] - m) * L2E);
            ssum += vals[k];
        }
        #pragma unroll
        for (int off = 8; off; off >>= 1) ssum += __shfl_xor_sync(~0u, ssum, off);
        const float rs = 1.0f / ssum;
        #pragma unroll
        for (int k = 0; k < 32; k++)
            ph[il * 536 + k * 16 + sub] = __float2half(vals[k] * rs);
    }
    __syncthreads();

    // ---- tensor-core aggregate ----
    {
        const int wid = tid >> 5, l = tid & 31;
        const int mt = wid >> 2, nt4 = wid & 3;
        const uint32_t pha = sb + PH
            + ((uint32_t)(mt * 16 + (l & 7) + ((l >> 3) & 1) * 8) * 536
               + ((l >> 4) & 1) * 8) * 2;
        const uint32_t xba = sb + XH
            + (uint32_t)(l & 15) * 144 + (uint32_t)(l >> 4) * 16
            + (uint32_t)nt4 * 32;

        float DA[2][4] = {{0.f,0.f,0.f,0.f},{0.f,0.f,0.f,0.f}};
        #pragma unroll 4
        for (int k16 = 0; k16 < 32; k16++) {
            uint32_t a[4];
            ldsm4(a, pha + k16 * 32);
            uint32_t bfr[4];
            ldsm4t(bfr, xba + k16 * 2304);   // 16 rows * 144B
            mma16816h(DA[0], a, bfr[0], bfr[1]);
            mma16816h(DA[1], a, bfr[2], bfr[3]);
        }
        const int row = mt * 16 + (l >> 2);
        #pragma unroll
        for (int nt8 = 0; nt8 < 2; nt8++) {
            const int col = nt4 * 16 + nt8 * 8 + (l & 3) * 2;
            *(float2*)(agg + row * 64 + col)       = make_float2(DA[nt8][0], DA[nt8][1]);
            *(float2*)(agg + (row + 8) * 64 + col) = make_float2(DA[nt8][2], DA[nt8][3]);
        }
    }
    __syncthreads();

    // ---- projections + BN partials ----
    {
        const int o = tid & 63, iq = tid >> 6;
        const float* wo1 = w1t + o * 68;
        const float* wo2 = w2t + o * 68;
        const float bo = bb[o];
        float psum = 0.f, psq = 0.f;
        #pragma unroll
        for (int m2 = 0; m2 < 8; m2++) {
            const int i = iq + 8 * m2;
            const float* ag = agg + i * 64;
            const float* xr = xb + (i0 + i) * DIM;
            float r0 = bo, r1 = 0.f;
            #pragma unroll
            for (int dd = 0; dd < 64; dd += 4) {
                float4 av = *(const float4*)(ag + dd);
                float4 w1 = *(const float4*)(wo1 + dd);
                float4 xv = *(const float4*)(xr + dd);
                float4 w2 = *(const float4*)(wo2 + dd);
                r0 = fmaf(av.x, w1.x, r0); r1 = fmaf(av.y, w1.y, r1);
                r0 = fmaf(av.z, w1.z, r0); r1 = fmaf(av.w, w1.w, r1);
                r0 = fmaf(xv.x, w2.x, r0); r1 = fmaf(xv.y, w2.y, r1);
                r0 = fmaf(xv.z, w2.z, r0); r1 = fmaf(xv.w, w2.w, r1);
            }
            const float r = r0 + r1;
            g_xout[((size_t)(b * SEQ + i0 + i)) * DIM + o] = r;
            psum += r;
            psq = fmaf(r, r, psq);
        }
        pt[iq * 64 + o]       = psum;
        pt[512 + iq * 64 + o] = psq;
    }
    __syncthreads();
    if (tid < 64) {
        float s = 0.f, sq = 0.f;
        #pragma unroll
        for (int q = 0; q < 8; q++) {
            s  += pt[q * 64 + tid];
            sq += pt[512 + q * 64 + tid];
        }
        g_part[blockIdx.x * 64 + tid]   = s;
        g_partsq[blockIdx.x * 64 + tid] = sq;
    }
}

// ---------------------------------------------------------------------------
// Kernel 3: BN finalize
// ---------------------------------------------------------------------------
__global__ void __launch_bounds__(128)
bnfin_kernel(const float* __restrict__ gamma, const float* __restrict__ beta)
{
    __shared__ float rs[4], rq[4];
    const int o = blockIdx.x, tid = threadIdx.x;
    float s = 0.f, sq = 0.f;
    for (int k = tid; k < 128; k += 128) {
        s  += g_part[k * 64 + o];
        sq += g_partsq[k * 64 + o];
    }
    #pragma unroll
    for (int off = 16; off; off >>= 1) {
        s  += __shfl_xor_sync(~0u, s, off);
        sq += __shfl_xor_sync(~0u, sq, off);
    }
    if ((tid & 31) == 0) { rs[tid >> 5] = s; rq[tid >> 5] = sq; }
    __syncthreads();
    if (tid == 0) {
        float ts = rs[0] + rs[1] + rs[2] + rs[3];
        float tq = rq[0] + rq[1] + rq[2] + rq[3];
        const float inv = 1.0f / (BATCH * SEQ);
        float mean = ts * inv;
        float var  = tq * inv - mean * mean;
        float sc = gamma[o] * rsqrtf(var + 1e-5f);
        g_bnscale[o] = sc;
        g_bnbias[o]  = beta[o] - mean * sc;
    }
}

// ---------------------------------------------------------------------------
// Kernel 4: normalize + SELU -> d_out
// ---------------------------------------------------------------------------
__global__ void __launch_bounds__(256)
apply_kernel(float* __restrict__ out)
{
    const int idx = blockIdx.x * 256 + threadIdx.x;
    const int o = idx & 63;
    float v = fmaf(g_xout[idx], g_bnscale[o], g_bnbias[o]);
    const float SC = 1.0507009873554805f, AL = 1.6732632423543772f;
    float neg = SC * AL * (ex2f(v * L2E) - 1.0f);
    out[idx] = v > 0.f ? SC * v : neg;
}

// ---------------------------------------------------------------------------
extern "C" void kernel_launch(void* const* d_in, const int* in_sizes, int n_in,
                              void* d_out, int out_size)
{
    const float* x      = (const float*)d_in[0];
    const float* Wattp  = (const float*)d_in[1];
    const float* battp  = (const float*)d_in[2];
    const float* attw   = (const float*)d_in[3];
    const float* Wwith  = (const float*)d_in[4];
    const float* bwith  = (const float*)d_in[5];
    const float* Wwo    = (const float*)d_in[6];
    const float* bwo    = (const float*)d_in[7];
    const float* gamma  = (const float*)d_in[8];
    const float* beta   = (const float*)d_in[9];
    float* out = (float*)d_out;

    cudaFuncSetAttribute(score_kernel, cudaFuncAttributeMaxDynamicSharedMemorySize, SC_SMEM);
    cudaFuncSetAttribute(agg_kernel,   cudaFuncAttributeMaxDynamicSharedMemorySize, AG_SMEM);

    score_kernel<<<BATCH * 36, 256, SC_SMEM>>>(x, Wattp, battp, attw);
    agg_kernel<<<128, 512, AG_SMEM>>>(x, Wwith, bwith, Wwo, bwo);
    bnfin_kernel<<<64, 128>>>(gamma, beta);
    apply_kernel<<<BATCH * SEQ * DIM / 256, 256>>>(out);
}